// round 11
// baseline (speedup 1.0000x reference)
#include <cuda_runtime.h>
#include <math.h>

#define NUM_STEPS 30

typedef unsigned long long ull;

// ---------------------------------------------------------------------------
// packed f32x2 helpers (sm_103a)
// ---------------------------------------------------------------------------
__device__ __forceinline__ ull pack2(float lo, float hi) {
    ull r; asm("mov.b64 %0, {%1, %2};" : "=l"(r) : "f"(lo), "f"(hi)); return r;
}
__device__ __forceinline__ void unpack2(ull v, float& lo, float& hi) {
    asm("mov.b64 {%0, %1}, %2;" : "=f"(lo), "=f"(hi) : "l"(v));
}
__device__ __forceinline__ ull mul2(ull a, ull b) {
    ull r; asm("mul.rn.f32x2 %0, %1, %2;" : "=l"(r) : "l"(a), "l"(b)); return r;
}
__device__ __forceinline__ ull fma2(ull a, ull b, ull c) {
    ull r; asm("fma.rn.f32x2 %0, %1, %2, %3;" : "=l"(r) : "l"(a), "l"(b), "l"(c)); return r;
}
__device__ __forceinline__ ull lerp2(ull a, ull b, ull t, ull omt) {
    return fma2(b, t, mul2(a, omt));
}

// ---------------------------------------------------------------------------
// fp32 Gauss-Jordan 4x4 inverse
// ---------------------------------------------------------------------------
__device__ void inv4x4_f32(const float* __restrict__ A, float* __restrict__ out) {
    float m[4][8];
    #pragma unroll
    for (int i = 0; i < 4; i++) {
        #pragma unroll
        for (int j = 0; j < 4; j++) m[i][j] = A[i * 4 + j];
        #pragma unroll
        for (int j = 0; j < 4; j++) m[i][4 + j] = (i == j) ? 1.0f : 0.0f;
    }
    #pragma unroll
    for (int col = 0; col < 4; col++) {
        int piv = col;
        float best = fabsf(m[col][col]);
        #pragma unroll
        for (int r = 0; r < 4; r++) {
            if (r > col) {
                float v = fabsf(m[r][col]);
                if (v > best) { best = v; piv = r; }
            }
        }
        if (piv != col) {
            #pragma unroll
            for (int j = 0; j < 8; j++) { float t = m[col][j]; m[col][j] = m[piv][j]; m[piv][j] = t; }
        }
        float inv = 1.0f / m[col][col];
        #pragma unroll
        for (int j = 0; j < 8; j++) m[col][j] *= inv;
        #pragma unroll
        for (int r = 0; r < 4; r++) {
            if (r != col) {
                float f = m[r][col];
                #pragma unroll
                for (int j = 0; j < 8; j++) m[r][j] = fmaf(-f, m[col][j], m[r][j]);
            }
        }
    }
    #pragma unroll
    for (int i = 0; i < 4; i++)
        #pragma unroll
        for (int j = 0; j < 4; j++)
            out[i * 4 + j] = m[i][4 + j];
}

// corner offsets for a cell
__device__ __forceinline__ void cell_offsets(int d0, int h0, int w0,
                                             int D, int H, int W, int HW, int* o) {
    int d1 = min(d0 + 1, D - 1);
    int h1 = min(h0 + 1, H - 1);
    int w1 = min(w0 + 1, W - 1);
    int rd0 = d0 * HW, rd1 = d1 * HW;
    int rh0 = h0 * W,  rh1 = h1 * W;
    o[0] = rd0 + rh0 + w0; o[1] = rd0 + rh0 + w1;
    o[2] = rd0 + rh1 + w0; o[3] = rd0 + rh1 + w1;
    o[4] = rd1 + rh0 + w0; o[5] = rd1 + rh0 + w1;
    o[6] = rd1 + rh1 + w0; o[7] = rd1 + rh1 + w1;
}

// ---------------------------------------------------------------------------
// dual-point kernel: point A corners in registers, point B corners in smem
// ---------------------------------------------------------------------------
__global__ __launch_bounds__(128, 6)
void deform_dual_kernel(const float* __restrict__ verts,
                        const float* __restrict__ affine,
                        const float* __restrict__ flow,
                        float* __restrict__ out,
                        int B, int N, int D, int H, int W,
                        int half, long long total)
{
    __shared__ ull s_c[128 * 13];          // 13-ull stride: 8 ull c01 + 8 f32 c2
    __shared__ float s_inv[2][16];

    int tid = threadIdx.x;
    if (tid < B) inv4x4_f32(affine + tid * 16, s_inv[tid]);
    __syncthreads();

    int gid = blockIdx.x * 128 + tid;
    if (gid >= half) return;

    int iA = gid;
    long long iBl = (long long)gid + half;
    bool hasB = (iBl < total);
    int iB = hasB ? (int)iBl : iA;

    int bA = iA / N, nA = iA - bA * N;
    int bB = iB / N, nB = iB - bB * N;

    const int HW  = H * W;
    const int DHW = D * HW;
    const float* baseA = flow + (size_t)bA * 3 * (size_t)DHW;
    const float* baseB = flow + (size_t)bB * 3 * (size_t)DHW;
    const float scale = 1.0f / (float)NUM_STEPS;
    const float dmax = (float)(D - 1), hmax = (float)(H - 1), wmax = (float)(W - 1);

    // ---- affine transforms (start positions recomputed at epilogue) ----
    float xdA, xhA, xwA, xdB, xhB, xwB;
    {
        const float* A4 = affine + bA * 16;
        size_t vb = ((size_t)bA * N + nA) * 3;
        float vx = __ldg(verts + vb + 0), vy = __ldg(verts + vb + 1), vz = __ldg(verts + vb + 2);
        xdA = A4[0]*vx + A4[1]*vy + A4[2] *vz + A4[3];
        xhA = A4[4]*vx + A4[5]*vy + A4[6] *vz + A4[7];
        xwA = A4[8]*vx + A4[9]*vy + A4[10]*vz + A4[11];
    }
    {
        const float* A4 = affine + bB * 16;
        size_t vb = ((size_t)bB * N + nB) * 3;
        float vx = __ldg(verts + vb + 0), vy = __ldg(verts + vb + 1), vz = __ldg(verts + vb + 2);
        xdB = A4[0]*vx + A4[1]*vy + A4[2] *vz + A4[3];
        xhB = A4[4]*vx + A4[5]*vy + A4[6] *vz + A4[7];
        xwB = A4[8]*vx + A4[9]*vy + A4[10]*vz + A4[11];
    }

    // per-thread private smem slot for B's corners
    ull*   scp = s_c + tid * 13;
    float* sf2 = (float*)(scp + 8);

    // cached cell state
    float cfdA = 1e30f, cfhA = 1e30f, cfwA = 1e30f;
    float cfdB = 1e30f, cfhB = 1e30f, cfwB = 1e30f;
    int cellA = -1, cellB = -1;
    ull  c01[8];
    float c2[8];

    #pragma unroll 1
    for (int s = 0; s < NUM_STEPS; s++) {
        // ---------- A: in-cell check / reload (registers) ----------
        float fdA = xdA - cfdA, fhA = xhA - cfhA, fwA = xwA - cfwA;
        {
            float mn = fminf(fdA, fminf(fhA, fwA));
            float mx = fmaxf(fdA, fmaxf(fhA, fwA));
            if (!(mn >= 0.0f && mx < 1.0f)) {
                float pdc = fminf(fmaxf(xdA, 0.0f), dmax);
                float phc = fminf(fmaxf(xhA, 0.0f), hmax);
                float pwc = fminf(fmaxf(xwA, 0.0f), wmax);
                float fd0 = floorf(pdc), fh0 = floorf(phc), fw0 = floorf(pwc);
                int d0 = (int)fd0, h0 = (int)fh0, w0 = (int)fw0;
                fdA = pdc - fd0; fhA = phc - fh0; fwA = pwc - fw0;
                cfdA = fd0; cfhA = fh0; cfwA = fw0;
                int ncell = (d0 << 20) | (h0 << 10) | w0;
                if (ncell != cellA) {
                    cellA = ncell;
                    int o[8];
                    cell_offsets(d0, h0, w0, D, H, W, HW, o);
                    const float* p0 = baseA;
                    const float* p1 = baseA + DHW;
                    const float* p2 = baseA + 2 * DHW;
                    #pragma unroll
                    for (int k = 0; k < 8; k++) {
                        float a0 = __ldg(p0 + o[k]);
                        float a1 = __ldg(p1 + o[k]);
                        c2[k]  = __ldg(p2 + o[k]);
                        c01[k] = pack2(a0, a1);
                    }
                }
            }
        }

        // ---------- B: in-cell check / reload (into smem) ----------
        float fdB = xdB - cfdB, fhB = xhB - cfhB, fwB = xwB - cfwB;
        {
            float mn = fminf(fdB, fminf(fhB, fwB));
            float mx = fmaxf(fdB, fmaxf(fhB, fwB));
            if (!(mn >= 0.0f && mx < 1.0f)) {
                float pdc = fminf(fmaxf(xdB, 0.0f), dmax);
                float phc = fminf(fmaxf(xhB, 0.0f), hmax);
                float pwc = fminf(fmaxf(xwB, 0.0f), wmax);
                float fd0 = floorf(pdc), fh0 = floorf(phc), fw0 = floorf(pwc);
                int d0 = (int)fd0, h0 = (int)fh0, w0 = (int)fw0;
                fdB = pdc - fd0; fhB = phc - fh0; fwB = pwc - fw0;
                cfdB = fd0; cfhB = fh0; cfwB = fw0;
                int ncell = (d0 << 20) | (h0 << 10) | w0;
                if (ncell != cellB) {
                    cellB = ncell;
                    int o[8];
                    cell_offsets(d0, h0, w0, D, H, W, HW, o);
                    const float* p0 = baseB;
                    const float* p1 = baseB + DHW;
                    const float* p2 = baseB + 2 * DHW;
                    #pragma unroll
                    for (int k = 0; k < 8; k++) {
                        float a0 = __ldg(p0 + o[k]);
                        float a1 = __ldg(p1 + o[k]);
                        sf2[k] = __ldg(p2 + o[k]);
                        scp[k] = pack2(a0, a1);
                    }
                }
            }
        }

        // ---------- A: packed lerp + update ----------
        {
            float omfw = 1.0f - fwA, omfh = 1.0f - fhA, omfd = 1.0f - fdA;
            ull W2  = pack2(fwA, fwA),   OW2 = pack2(omfw, omfw);
            ull H2  = pack2(fhA, fhA),   OH2 = pack2(omfh, omfh);
            ull D2  = pack2(fdA, fdA),   OD2 = pack2(omfd, omfd);
            ull l00 = lerp2(c01[0], c01[1], W2, OW2);
            ull l01 = lerp2(c01[2], c01[3], W2, OW2);
            ull l10 = lerp2(c01[4], c01[5], W2, OW2);
            ull l11 = lerp2(c01[6], c01[7], W2, OW2);
            ull m0  = lerp2(l00, l01, H2, OH2);
            ull m1  = lerp2(l10, l11, H2, OH2);
            ull r01 = lerp2(m0, m1, D2, OD2);
            float s0, s1;
            unpack2(r01, s0, s1);
            float q00 = c2[0] * omfw + c2[1] * fwA;
            float q01 = c2[2] * omfw + c2[3] * fwA;
            float q10 = c2[4] * omfw + c2[5] * fwA;
            float q11 = c2[6] * omfw + c2[7] * fwA;
            float q0  = q00 * omfh + q01 * fhA;
            float q1  = q10 * omfh + q11 * fhA;
            float s2  = q0 * omfd + q1 * fdA;
            xdA = fmaf(s0, scale, xdA);
            xhA = fmaf(s1, scale, xhA);
            xwA = fmaf(s2, scale, xwA);
        }

        // ---------- B: packed lerp from smem + update ----------
        {
            float omfw = 1.0f - fwB, omfh = 1.0f - fhB, omfd = 1.0f - fdB;
            ull W2  = pack2(fwB, fwB),   OW2 = pack2(omfw, omfw);
            ull H2  = pack2(fhB, fhB),   OH2 = pack2(omfh, omfh);
            ull D2  = pack2(fdB, fdB),   OD2 = pack2(omfd, omfd);
            ull l00 = lerp2(scp[0], scp[1], W2, OW2);
            ull l01 = lerp2(scp[2], scp[3], W2, OW2);
            ull l10 = lerp2(scp[4], scp[5], W2, OW2);
            ull l11 = lerp2(scp[6], scp[7], W2, OW2);
            ull m0  = lerp2(l00, l01, H2, OH2);
            ull m1  = lerp2(l10, l11, H2, OH2);
            ull r01 = lerp2(m0, m1, D2, OD2);
            float s0, s1;
            unpack2(r01, s0, s1);
            float q00 = sf2[0] * omfw + sf2[1] * fwB;
            float q01 = sf2[2] * omfw + sf2[3] * fwB;
            float q10 = sf2[4] * omfw + sf2[5] * fwB;
            float q11 = sf2[6] * omfw + sf2[7] * fwB;
            float q0  = q00 * omfh + q01 * fhB;
            float q1  = q10 * omfh + q11 * fhB;
            float s2  = q0 * omfd + q1 * fdB;
            xdB = fmaf(s0, scale, xdB);
            xhB = fmaf(s1, scale, xhB);
            xwB = fmaf(s2, scale, xwB);
        }
    }

    // ---------- epilogue: recompute starts, write outputs ----------
    {
        const float* A4 = affine + bA * 16;
        size_t vb = ((size_t)bA * N + nA) * 3;
        float vx = __ldg(verts + vb + 0), vy = __ldg(verts + vb + 1), vz = __ldg(verts + vb + 2);
        float px = A4[0]*vx + A4[1]*vy + A4[2] *vz + A4[3];
        float py = A4[4]*vx + A4[5]*vy + A4[6] *vz + A4[7];
        float pz = A4[8]*vx + A4[9]*vy + A4[10]*vz + A4[11];
        float fix = xdA - px, fiy = xhA - py, fiz = xwA - pz;
        const float* Inv = s_inv[bA];
        float ox = Inv[0]*xdA + Inv[1]*xhA + Inv[2] *xwA + Inv[3];
        float oy = Inv[4]*xdA + Inv[5]*xhA + Inv[6] *xwA + Inv[7];
        float oz = Inv[8]*xdA + Inv[9]*xhA + Inv[10]*xwA + Inv[11];
        size_t pb = ((size_t)bA * N + nA) * 3;
        out[pb + 0] = ox; out[pb + 1] = oy; out[pb + 2] = oz;
        size_t fb = (size_t)B * N * 3 + ((size_t)bA * 3) * (size_t)N + nA;
        out[fb + 0 * (size_t)N] = fix;
        out[fb + 1 * (size_t)N] = fiy;
        out[fb + 2 * (size_t)N] = fiz;
    }
    if (hasB) {
        const float* A4 = affine + bB * 16;
        size_t vb = ((size_t)bB * N + nB) * 3;
        float vx = __ldg(verts + vb + 0), vy = __ldg(verts + vb + 1), vz = __ldg(verts + vb + 2);
        float px = A4[0]*vx + A4[1]*vy + A4[2] *vz + A4[3];
        float py = A4[4]*vx + A4[5]*vy + A4[6] *vz + A4[7];
        float pz = A4[8]*vx + A4[9]*vy + A4[10]*vz + A4[11];
        float fix = xdB - px, fiy = xhB - py, fiz = xwB - pz;
        const float* Inv = s_inv[bB];
        float ox = Inv[0]*xdB + Inv[1]*xhB + Inv[2] *xwB + Inv[3];
        float oy = Inv[4]*xdB + Inv[5]*xhB + Inv[6] *xwB + Inv[7];
        float oz = Inv[8]*xdB + Inv[9]*xhB + Inv[10]*xwB + Inv[11];
        size_t pb = ((size_t)bB * N + nB) * 3;
        out[pb + 0] = ox; out[pb + 1] = oy; out[pb + 2] = oz;
        size_t fb = (size_t)B * N * 3 + ((size_t)bB * 3) * (size_t)N + nB;
        out[fb + 0 * (size_t)N] = fix;
        out[fb + 1 * (size_t)N] = fiy;
        out[fb + 2 * (size_t)N] = fiz;
    }
}

// ---------------------------------------------------------------------------
// fallback: round-9 single-point kernel (B > 2 or tiny workloads)
// ---------------------------------------------------------------------------
__global__ __launch_bounds__(128, 8)
void deform_plain_kernel(const float* __restrict__ verts,
                         const float* __restrict__ affine,
                         const float* __restrict__ flow,
                         float* __restrict__ out,
                         int B, int N, int D, int H, int W)
{
    __shared__ float s_inv[2][16];
    int gid = blockIdx.x * blockDim.x + threadIdx.x;
    long long total = (long long)B * N;
    long long g0 = (long long)blockIdx.x * blockDim.x;
    long long g1 = min(g0 + blockDim.x - 1, total - 1);
    int bmin = (int)(g0 / N);
    int bmax = (int)(g1 / N);
    if (threadIdx.x == 0) {
        inv4x4_f32(affine + bmin * 16, s_inv[0]);
        if (bmax != bmin) inv4x4_f32(affine + bmax * 16, s_inv[1]);
    }
    __syncthreads();
    if (gid >= total) return;
    int b = gid / N, n = gid - b * N;

    const float* A = affine + b * 16;
    size_t vbase = ((size_t)b * N + n) * 3;
    float vx = verts[vbase + 0], vy = verts[vbase + 1], vz = verts[vbase + 2];
    float px = A[0]*vx + A[1]*vy + A[2] *vz + A[3];
    float py = A[4]*vx + A[5]*vy + A[6] *vz + A[7];
    float pz = A[8]*vx + A[9]*vy + A[10]*vz + A[11];

    const int HW = H * W, DHW = D * HW;
    const float* base = flow + (size_t)b * 3 * (size_t)DHW;
    const float scale = 1.0f / (float)NUM_STEPS;
    const float dmax = (float)(D - 1), hmax = (float)(H - 1), wmax = (float)(W - 1);

    float xd = px, xh = py, xw = pz;
    float cfd = 1e30f, cfh = 1e30f, cfw = 1e30f;
    int cell = -1;
    ull c01[8]; float c2[8];

    #pragma unroll 1
    for (int s = 0; s < NUM_STEPS; s++) {
        float fd = xd - cfd, fh = xh - cfh, fw = xw - cfw;
        float mn = fminf(fd, fminf(fh, fw));
        float mx = fmaxf(fd, fmaxf(fh, fw));
        if (!(mn >= 0.0f && mx < 1.0f)) {
            float pdc = fminf(fmaxf(xd, 0.0f), dmax);
            float phc = fminf(fmaxf(xh, 0.0f), hmax);
            float pwc = fminf(fmaxf(xw, 0.0f), wmax);
            float fd0 = floorf(pdc), fh0 = floorf(phc), fw0 = floorf(pwc);
            int d0 = (int)fd0, h0 = (int)fh0, w0 = (int)fw0;
            fd = pdc - fd0; fh = phc - fh0; fw = pwc - fw0;
            cfd = fd0; cfh = fh0; cfw = fw0;
            int ncell = (d0 << 20) | (h0 << 10) | w0;
            if (ncell != cell) {
                cell = ncell;
                int o[8];
                cell_offsets(d0, h0, w0, D, H, W, HW, o);
                const float* p0 = base;
                const float* p1 = base + DHW;
                const float* p2 = base + 2 * DHW;
                #pragma unroll
                for (int k = 0; k < 8; k++) {
                    float a0 = __ldg(p0 + o[k]);
                    float a1 = __ldg(p1 + o[k]);
                    c2[k]  = __ldg(p2 + o[k]);
                    c01[k] = pack2(a0, a1);
                }
            }
        }
        float omfw = 1.0f - fw, omfh = 1.0f - fh, omfd = 1.0f - fd;
        ull W2 = pack2(fw, fw), OW2 = pack2(omfw, omfw);
        ull H2 = pack2(fh, fh), OH2 = pack2(omfh, omfh);
        ull D2 = pack2(fd, fd), OD2 = pack2(omfd, omfd);
        ull l00 = lerp2(c01[0], c01[1], W2, OW2);
        ull l01 = lerp2(c01[2], c01[3], W2, OW2);
        ull l10 = lerp2(c01[4], c01[5], W2, OW2);
        ull l11 = lerp2(c01[6], c01[7], W2, OW2);
        ull m0 = lerp2(l00, l01, H2, OH2);
        ull m1 = lerp2(l10, l11, H2, OH2);
        ull r01 = lerp2(m0, m1, D2, OD2);
        float s0, s1; unpack2(r01, s0, s1);
        float q00 = c2[0]*omfw + c2[1]*fw;
        float q01 = c2[2]*omfw + c2[3]*fw;
        float q10 = c2[4]*omfw + c2[5]*fw;
        float q11 = c2[6]*omfw + c2[7]*fw;
        float q0 = q00*omfh + q01*fh;
        float q1 = q10*omfh + q11*fh;
        float s2 = q0*omfd + q1*fd;
        xd = fmaf(s0, scale, xd);
        xh = fmaf(s1, scale, xh);
        xw = fmaf(s2, scale, xw);
    }

    float fix = xd - px, fiy = xh - py, fiz = xw - pz;
    const float* Inv = s_inv[b - bmin];
    float ox = Inv[0]*xd + Inv[1]*xh + Inv[2] *xw + Inv[3];
    float oy = Inv[4]*xd + Inv[5]*xh + Inv[6] *xw + Inv[7];
    float oz = Inv[8]*xd + Inv[9]*xh + Inv[10]*xw + Inv[11];
    size_t pb = ((size_t)b * N + n) * 3;
    out[pb + 0] = ox; out[pb + 1] = oy; out[pb + 2] = oz;
    size_t fb = (size_t)B * N * 3 + ((size_t)b * 3) * (size_t)N + n;
    out[fb + 0 * (size_t)N] = fix;
    out[fb + 1 * (size_t)N] = fiy;
    out[fb + 2 * (size_t)N] = fiz;
}

extern "C" void kernel_launch(void* const* d_in, const int* in_sizes, int n_in,
                              void* d_out, int out_size) {
    const float* verts  = (const float*)d_in[0];
    const float* affine = (const float*)d_in[1];
    const float* flow   = (const float*)d_in[2];
    float* out = (float*)d_out;

    int B = in_sizes[1] / 16;
    int N = in_sizes[0] / (3 * B);
    long long dhw = (long long)in_sizes[2] / (3LL * B);
    int D = (int)llrint(cbrt((double)dhw));
    int H = D, W = D;

    long long total = (long long)B * N;

    if (B <= 2 && total >= 2) {
        int half = (int)((total + 1) / 2);
        int blocks = (half + 127) / 128;
        deform_dual_kernel<<<blocks, 128>>>(verts, affine, flow, out,
                                            B, N, D, H, W, half, total);
    } else {
        int threads = 128;
        int blocks = (int)((total + threads - 1) / threads);
        deform_plain_kernel<<<blocks, threads>>>(verts, affine, flow, out,
                                                 B, N, D, H, W);
    }
}

// round 12
// speedup vs baseline: 1.7210x; 1.7210x over previous
#include <cuda_runtime.h>
#include <math.h>

#define NUM_STEPS 30

typedef unsigned long long ull;

// ---------------------------------------------------------------------------
// packed f32x2 helpers (sm_103a)
// ---------------------------------------------------------------------------
__device__ __forceinline__ ull pack2(float lo, float hi) {
    ull r; asm("mov.b64 %0, {%1, %2};" : "=l"(r) : "f"(lo), "f"(hi)); return r;
}
__device__ __forceinline__ void unpack2(ull v, float& lo, float& hi) {
    asm("mov.b64 {%0, %1}, %2;" : "=f"(lo), "=f"(hi) : "l"(v));
}
__device__ __forceinline__ ull mul2(ull a, ull b) {
    ull r; asm("mul.rn.f32x2 %0, %1, %2;" : "=l"(r) : "l"(a), "l"(b)); return r;
}
__device__ __forceinline__ ull fma2(ull a, ull b, ull c) {
    ull r; asm("fma.rn.f32x2 %0, %1, %2, %3;" : "=l"(r) : "l"(a), "l"(b), "l"(c)); return r;
}
__device__ __forceinline__ ull lerp2(ull a, ull b, ull t, ull omt) {
    return fma2(b, t, mul2(a, omt));
}

// ---------------------------------------------------------------------------
// fp32 Gauss-Jordan 4x4 inverse (well-conditioned input)
// ---------------------------------------------------------------------------
__device__ void inv4x4_f32(const float* __restrict__ A, float* __restrict__ out) {
    float m[4][8];
    #pragma unroll
    for (int i = 0; i < 4; i++) {
        #pragma unroll
        for (int j = 0; j < 4; j++) m[i][j] = A[i * 4 + j];
        #pragma unroll
        for (int j = 0; j < 4; j++) m[i][4 + j] = (i == j) ? 1.0f : 0.0f;
    }
    #pragma unroll
    for (int col = 0; col < 4; col++) {
        int piv = col;
        float best = fabsf(m[col][col]);
        #pragma unroll
        for (int r = 0; r < 4; r++) {
            if (r > col) {
                float v = fabsf(m[r][col]);
                if (v > best) { best = v; piv = r; }
            }
        }
        if (piv != col) {
            #pragma unroll
            for (int j = 0; j < 8; j++) { float t = m[col][j]; m[col][j] = m[piv][j]; m[piv][j] = t; }
        }
        float inv = 1.0f / m[col][col];
        #pragma unroll
        for (int j = 0; j < 8; j++) m[col][j] *= inv;
        #pragma unroll
        for (int r = 0; r < 4; r++) {
            if (r != col) {
                float f = m[r][col];
                #pragma unroll
                for (int j = 0; j < 8; j++) m[r][j] = fmaf(-f, m[col][j], m[r][j]);
            }
        }
    }
    #pragma unroll
    for (int i = 0; i < 4; i++)
        #pragma unroll
        for (int j = 0; j < 4; j++)
            out[i * 4 + j] = m[i][4 + j];
}

// load the (w0, w1) corner pair for one row of one channel
// pairable: o0 even and w1 == w0+1 -> single aligned float2 (1 wavefront)
__device__ __forceinline__ void load_pair(const float* __restrict__ p, int o0, int o1,
                                          bool pairable, float& a, float& b) {
    if (pairable) {
        float2 v = __ldg((const float2*)(p + o0));
        a = v.x; b = v.y;
    } else {
        a = __ldg(p + o0);
        b = __ldg(p + o1);
    }
}

// ---------------------------------------------------------------------------
// single fused kernel — 128-thread blocks, paired corner loads
// ---------------------------------------------------------------------------
__global__ __launch_bounds__(128, 7)
void deform_kernel(const float* __restrict__ verts,
                   const float* __restrict__ affine,
                   const float* __restrict__ flow,
                   float* __restrict__ out,
                   int B, int N, int D, int H, int W)
{
    __shared__ float s_inv[2][16];   // a block spans at most 2 batch values

    int gid = blockIdx.x * blockDim.x + threadIdx.x;
    long long total = (long long)B * N;

    long long g0 = (long long)blockIdx.x * blockDim.x;
    long long g1 = min(g0 + blockDim.x - 1, total - 1);
    int bmin = (int)(g0 / N);
    int bmax = (int)(g1 / N);

    if (threadIdx.x == 0) {
        inv4x4_f32(affine + bmin * 16, s_inv[0]);
        if (bmax != bmin) inv4x4_f32(affine + bmax * 16, s_inv[1]);
    }
    __syncthreads();

    if (gid >= total) return;
    int b = gid / N;
    int n = gid - b * N;

    // ---- affine transform ----
    const float* A = affine + b * 16;
    size_t vbase = ((size_t)b * N + n) * 3;
    float vx = verts[vbase + 0];
    float vy = verts[vbase + 1];
    float vz = verts[vbase + 2];

    float px = A[0] * vx + A[1] * vy + A[2]  * vz + A[3];
    float py = A[4] * vx + A[5] * vy + A[6]  * vz + A[7];
    float pz = A[8] * vx + A[9] * vy + A[10] * vz + A[11];

    const int HW  = H * W;
    const int DHW = D * HW;
    const float* base = flow + (size_t)b * 3 * (size_t)DHW;
    const float scale = 1.0f / (float)NUM_STEPS;
    const float dmax = (float)(D - 1), hmax = (float)(H - 1), wmax = (float)(W - 1);

    float xd = px, xh = py, xw = pz;

    float cfd = 1e30f, cfh = 1e30f, cfw = 1e30f;
    int cell = -1;
    ull  c01[8];
    float c2[8];

    #pragma unroll 1
    for (int s = 0; s < NUM_STEPS; s++) {
        float fd = xd - cfd;
        float fh = xh - cfh;
        float fw = xw - cfw;

        float mn = fminf(fd, fminf(fh, fw));
        float mx = fmaxf(fd, fmaxf(fh, fw));
        if (!(mn >= 0.0f && mx < 1.0f)) {
            float pdc = fminf(fmaxf(xd, 0.0f), dmax);
            float phc = fminf(fmaxf(xh, 0.0f), hmax);
            float pwc = fminf(fmaxf(xw, 0.0f), wmax);
            float fd0 = floorf(pdc), fh0 = floorf(phc), fw0 = floorf(pwc);
            int d0 = (int)fd0, h0 = (int)fh0, w0 = (int)fw0;
            fd = pdc - fd0; fh = phc - fh0; fw = pwc - fw0;
            cfd = fd0; cfh = fh0; cfw = fw0;

            int ncell = (d0 << 20) | (h0 << 10) | w0;
            if (ncell != cell) {
                cell = ncell;
                int d1 = min(d0 + 1, D - 1);
                int h1 = min(h0 + 1, H - 1);
                int w1 = min(w0 + 1, W - 1);
                int r0 = d0 * HW + h0 * W;
                int r1 = d0 * HW + h1 * W;
                int r2 = d1 * HW + h0 * W;
                int r3 = d1 * HW + h1 * W;
                const float* p0 = base;
                const float* p1 = base + DHW;
                const float* p2 = base + 2 * DHW;
                bool pairable = (((w0 & 1) == 0) && (w1 == w0 + 1));
                int ro[4] = {r0, r1, r2, r3};
                #pragma unroll
                for (int k = 0; k < 4; k++) {
                    int o0 = ro[k] + w0;
                    int o1 = ro[k] + w1;
                    float a0, b0v, a1, b1v, a2, b2v;
                    load_pair(p0, o0, o1, pairable, a0, b0v);
                    load_pair(p1, o0, o1, pairable, a1, b1v);
                    load_pair(p2, o0, o1, pairable, a2, b2v);
                    c01[2 * k + 0] = pack2(a0, a1);
                    c01[2 * k + 1] = pack2(b0v, b1v);
                    c2[2 * k + 0]  = a2;
                    c2[2 * k + 1]  = b2v;
                }
            }
        }

        float omfw = 1.0f - fw, omfh = 1.0f - fh, omfd = 1.0f - fd;
        ull W2  = pack2(fw, fw),   OW2 = pack2(omfw, omfw);
        ull H2  = pack2(fh, fh),   OH2 = pack2(omfh, omfh);
        ull D2  = pack2(fd, fd),   OD2 = pack2(omfd, omfd);

        ull l00 = lerp2(c01[0], c01[1], W2, OW2);
        ull l01 = lerp2(c01[2], c01[3], W2, OW2);
        ull l10 = lerp2(c01[4], c01[5], W2, OW2);
        ull l11 = lerp2(c01[6], c01[7], W2, OW2);
        ull m0  = lerp2(l00, l01, H2, OH2);
        ull m1  = lerp2(l10, l11, H2, OH2);
        ull r01 = lerp2(m0, m1, D2, OD2);
        float s0, s1;
        unpack2(r01, s0, s1);

        float q00 = c2[0] * omfw + c2[1] * fw;
        float q01 = c2[2] * omfw + c2[3] * fw;
        float q10 = c2[4] * omfw + c2[5] * fw;
        float q11 = c2[6] * omfw + c2[7] * fw;
        float q0  = q00 * omfh + q01 * fh;
        float q1  = q10 * omfh + q11 * fh;
        float s2  = q0 * omfd + q1 * fd;

        xd = fmaf(s0, scale, xd);
        xh = fmaf(s1, scale, xh);
        xw = fmaf(s2, scale, xw);
    }

    // ---- outputs ----
    float fix = xd - px, fiy = xh - py, fiz = xw - pz;

    const float* Inv = s_inv[b - bmin];
    float ox = Inv[0] * xd + Inv[1] * xh + Inv[2]  * xw + Inv[3];
    float oy = Inv[4] * xd + Inv[5] * xh + Inv[6]  * xw + Inv[7];
    float oz = Inv[8] * xd + Inv[9] * xh + Inv[10] * xw + Inv[11];

    size_t pb = ((size_t)b * N + n) * 3;
    out[pb + 0] = ox;
    out[pb + 1] = oy;
    out[pb + 2] = oz;

    size_t fb = (size_t)B * N * 3 + ((size_t)b * 3) * (size_t)N + n;
    out[fb + 0 * (size_t)N] = fix;
    out[fb + 1 * (size_t)N] = fiy;
    out[fb + 2 * (size_t)N] = fiz;
}

extern "C" void kernel_launch(void* const* d_in, const int* in_sizes, int n_in,
                              void* d_out, int out_size) {
    const float* verts  = (const float*)d_in[0];
    const float* affine = (const float*)d_in[1];
    const float* flow   = (const float*)d_in[2];
    float* out = (float*)d_out;

    int B = in_sizes[1] / 16;
    int N = in_sizes[0] / (3 * B);
    long long dhw = (long long)in_sizes[2] / (3LL * B);
    int D = (int)llrint(cbrt((double)dhw));
    int H = D, W = D;

    long long total = (long long)B * N;
    int threads = 128;
    int blocks = (int)((total + threads - 1) / threads);
    deform_kernel<<<blocks, threads>>>(verts, affine, flow, out, B, N, D, H, W);
}